// round 1
// baseline (speedup 1.0000x reference)
#include <cuda_runtime.h>

// Problem constants
#define BB 2
#define FF 512
#define HH 192
#define WW 192
#define TT 8
#define HW (HH * WW)

__device__ __constant__ float kFAR = 100.0f;

// Scratch (device globals: allocation-free rule)
// per face: 3x float4 = {A0,B0,C0,A1}, {B1,C1,iz0,iz1}, {iz2,-,-,-}
__device__ float4 g_coef[BB * FF * 3];
// per face bbox: {xmin, xmax, ymin, ymax}
__device__ float4 g_bbox[BB * FF];

__global__ void preprocess_kernel(const float* __restrict__ faces) {
    int i = blockIdx.x * blockDim.x + threadIdx.x;
    if (i >= BB * FF) return;
    const float* f = faces + i * 9;
    float x0 = f[0], y0 = f[1], z0 = f[2];
    float x1 = f[3], y1 = f[4], z1 = f[5];
    float x2 = f[6], y2 = f[7], z2 = f[8];

    float det = (x1 - x0) * (y2 - y0) - (x2 - x0) * (y1 - y0);
    bool ok = fabsf(det) > 1e-8f;
    float inv_det = ok ? (1.0f / det) : 1.0f;

    // w0 = A0 + B0*px + C0*py ; w1 = A1 + B1*px + C1*py ; w2 = 1 - w0 - w1
    float A0 = (x1 * y2 - x2 * y1) * inv_det;
    float B0 = (y1 - y2) * inv_det;
    float C0 = (x2 - x1) * inv_det;
    float A1 = (x2 * y0 - x0 * y2) * inv_det;
    float B1 = (y2 - y0) * inv_det;
    float C1 = (x0 - x2) * inv_det;

    g_coef[i * 3 + 0] = make_float4(A0, B0, C0, A1);
    g_coef[i * 3 + 1] = make_float4(B1, C1, 1.0f / z0, 1.0f / z1);
    g_coef[i * 3 + 2] = make_float4(1.0f / z2, 0.0f, 0.0f, 0.0f);

    float xmin = fminf(x0, fminf(x1, x2)), xmax = fmaxf(x0, fmaxf(x1, x2));
    float ymin = fminf(y0, fminf(y1, y2)), ymax = fmaxf(y0, fmaxf(y1, y2));
    if (!ok) { xmin = 1e30f; xmax = -1e30f; }  // never overlaps any tile
    g_bbox[i] = make_float4(xmin, xmax, ymin, ymax);
}

#define TILE 16
#define NTHREADS 256
#define NWARPS 8  // FF / 64 faces per warp

__global__ __launch_bounds__(NTHREADS)
void raster_kernel(const float* __restrict__ textures, float* __restrict__ out) {
    __shared__ float4 s_coef[FF * 3];   // 24 KB (worst case all faces survive)
    __shared__ int    s_list[FF];
    __shared__ int    s_cnt[NWARPS];

    const int tid  = threadIdx.y * TILE + threadIdx.x;
    const int warp = tid >> 5;
    const int lane = tid & 31;
    const int b = blockIdx.z;

    // Tile bounds in NDC (pixel-center extremes)
    const int ix0 = blockIdx.x * TILE;
    const int iy0 = blockIdx.y * TILE;
    const float pxmin = (2.0f * (ix0 + 0.5f) - WW) / WW;
    const float pxmax = (2.0f * (ix0 + TILE - 1 + 0.5f) - WW) / WW;
    const float pymin = (2.0f * (iy0 + 0.5f) - HH) / HH;
    const float pymax = (2.0f * (iy0 + TILE - 1 + 0.5f) - HH) / HH;

    // --- Phase 1: order-preserving cull+compact (warp w owns faces [64w, 64w+64))
    const float4* bb = g_bbox + b * FF;
    unsigned ball0, ball1;
    {
        int fid = warp * 64 + lane;
        float4 v = bb[fid];
        bool p = (v.x <= pxmax) && (v.y >= pxmin) && (v.z <= pymax) && (v.w >= pymin);
        ball0 = __ballot_sync(0xffffffffu, p);
        fid += 32;
        v = bb[fid];
        p = (v.x <= pxmax) && (v.y >= pxmin) && (v.z <= pymax) && (v.w >= pymin);
        ball1 = __ballot_sync(0xffffffffu, p);
    }
    if (lane == 0) s_cnt[warp] = __popc(ball0) + __popc(ball1);
    __syncthreads();

    int offset = 0, total = 0;
    #pragma unroll
    for (int w = 0; w < NWARPS; w++) {
        int c = s_cnt[w];
        if (w < warp) offset += c;
        total += c;
    }

    {
        unsigned lt = (1u << lane) - 1u;
        if (ball0 & (1u << lane))
            s_list[offset + __popc(ball0 & lt)] = warp * 64 + lane;
        int base = offset + __popc(ball0);
        if (ball1 & (1u << lane))
            s_list[base + __popc(ball1 & lt)] = warp * 64 + 32 + lane;
    }
    __syncthreads();

    // --- Phase 2: gather surviving faces' coefficients into shared
    const float4* gc = g_coef + b * FF * 3;
    for (int i = tid; i < total; i += NTHREADS) {
        int f = s_list[i];
        s_coef[i * 3 + 0] = gc[f * 3 + 0];
        s_coef[i * 3 + 1] = gc[f * 3 + 1];
        s_coef[i * 3 + 2] = gc[f * 3 + 2];
    }
    __syncthreads();

    // --- Phase 3: per-pixel z-test over compacted list
    const int ix = ix0 + threadIdx.x;
    const int iy = iy0 + threadIdx.y;
    const float px = (2.0f * (ix + 0.5f) - WW) / WW;
    const float py = (2.0f * (iy + 0.5f) - HH) / HH;

    float best_invd = 0.01f;  // 1/FAR: must strictly beat this (depth < FAR)
    int best = -1;
    for (int i = 0; i < total; i++) {
        float4 c0 = s_coef[i * 3 + 0];
        float4 c1 = s_coef[i * 3 + 1];
        float4 c2 = s_coef[i * 3 + 2];
        float w0 = fmaf(c0.z, py, fmaf(c0.y, px, c0.x));
        float w1 = fmaf(c1.y, py, fmaf(c1.x, px, c0.w));
        float w2 = 1.0f - w0 - w1;
        float invd = fmaf(w2, c2.x, fmaf(w1, c1.w, w0 * c1.z));
        bool inside = (w0 >= 0.0f) && (w1 >= 0.0f) && (w2 >= 0.0f);
        if (inside && invd > best_invd && invd <= 2.0f) {  // 2.0 = 1/NEAR
            best_invd = invd;
            best = i;
        }
    }

    // --- Epilogue: texture interpolation + writes
    const int pix = iy * WW + ix;
    float* feature = out;                      // (B, 9, H, W)
    float* fim  = out + (size_t)BB * 9 * HW;   // (B, H, W) as float
    float* dmap = fim + (size_t)BB * HW;       // (B, H, W)
    float* fptr = feature + (size_t)b * 9 * HW + pix;

    if (best >= 0) {
        float4 c0 = s_coef[best * 3 + 0];
        float4 c1 = s_coef[best * 3 + 1];
        float w0 = fmaf(c0.z, py, fmaf(c0.y, px, c0.x));
        float w1 = fmaf(c1.y, py, fmaf(c1.x, px, c0.w));
        float w2 = 1.0f - w0 - w1;
        int f = s_list[best];
        const float4* tx = (const float4*)(textures + ((size_t)(b * FF + f) * 3) * TT);
        // tx: vertex k rows of 8 floats = 2 float4 each
        float4 t0a = tx[0], t0b = tx[1];
        float4 t1a = tx[2], t1b = tx[3];
        float4 t2a = tx[4], t2b = tx[5];
        float r[8];
        r[0] = w0 * t0a.x + w1 * t1a.x + w2 * t2a.x;
        r[1] = w0 * t0a.y + w1 * t1a.y + w2 * t2a.y;
        r[2] = w0 * t0a.z + w1 * t1a.z + w2 * t2a.z;
        r[3] = w0 * t0a.w + w1 * t1a.w + w2 * t2a.w;
        r[4] = w0 * t0b.x + w1 * t1b.x + w2 * t2b.x;
        r[5] = w0 * t0b.y + w1 * t1b.y + w2 * t2b.y;
        r[6] = w0 * t0b.z + w1 * t1b.z + w2 * t2b.z;
        r[7] = w0 * t0b.w + w1 * t1b.w + w2 * t2b.w;
        #pragma unroll
        for (int t = 0; t < 8; t++) fptr[(size_t)t * HW] = r[t];
        fptr[(size_t)8 * HW] = 1.0f;
        fim[(size_t)b * HW + pix]  = (float)f;
        dmap[(size_t)b * HW + pix] = 1.0f / best_invd;
    } else {
        #pragma unroll
        for (int t = 0; t < 8; t++) fptr[(size_t)t * HW] = 0.0f;
        fptr[(size_t)8 * HW] = 0.0f;
        fim[(size_t)b * HW + pix]  = -1.0f;
        dmap[(size_t)b * HW + pix] = kFAR;
    }
}

extern "C" void kernel_launch(void* const* d_in, const int* in_sizes, int n_in,
                              void* d_out, int out_size) {
    const float* faces    = (const float*)d_in[0];    // (B, F, 3, 3)
    const float* textures = (const float*)d_in[1];    // (B, F, 3, T)
    float* out = (float*)d_out;

    preprocess_kernel<<<(BB * FF + 255) / 256, 256>>>(faces);

    dim3 blk(TILE, TILE, 1);
    dim3 grd(WW / TILE, HH / TILE, BB);
    raster_kernel<<<grd, blk>>>(textures, out);
}